// round 16
// baseline (speedup 1.0000x reference)
#include <cuda_runtime.h>
#include <cuda_fp16.h>
#include <cfloat>

// Problem constants
#define NB    256     // batch
#define NN    1152    // input capsules
#define DIN   8       // input capsule dim
#define NC    10      // output capsules
#define NU    16      // output cap dim
#define TPB   512
#define KROWS 9       // rows per thread (1152 / 128 gg-groups)
#define WTOT  (NC * NN * DIN * NU)   // 1,474,560 halves
#define INTOT (NB * NN * DIN)        // 2,359,296 floats

// Warp-contiguous permuted fp16 W (2.95 MB), 16-warp layout (as R11).
// 16-byte chunk index: ((((c*9 + k)*16 + w)*4 + m)*8 + g3)*4 + u4
//   holds W[c][n][2m][u4*4..+3] , W[c][n][2m+1][u4*4..+3]  (8 halves)
//   where n = k*128 + w*8 + g3. For fixed (k,m) a warp's 32 lanes hit 32
//   consecutive chunks = 512B = 4 cache lines per LDG.128.
__device__ __align__(16) __half W_half[WTOT];

__device__ __forceinline__ float ex2f(float x) {
    float y; asm("ex2.approx.f32 %0, %1;" : "=f"(y) : "f"(x)); return y;
}

__global__ __launch_bounds__(512, 4)
void convert_W_kernel(const float* __restrict__ W)
{
    const int nchunks = WTOT / 8;                     // 184,320 16B-chunks
    int o = blockIdx.x * blockDim.x + threadIdx.x;
    for (; o < nchunks; o += gridDim.x * blockDim.x) {
        const int u4 = o & 3;
        const int g3 = (o >> 2) & 7;
        const int m  = (o >> 5) & 3;
        const int w  = (o >> 7) & 15;
        const int ck = o >> 11;          // c*9 + k
        const int k  = ck % 9;
        const int c  = ck / 9;
        const int n  = k * 128 + w * 8 + g3;
        const int i0 = 2 * m;
        const size_t s0 = (((size_t)c * NN + n) * 8 + i0) * 4 + u4;
        float4 wa = reinterpret_cast<const float4*>(W)[s0];
        float4 wb = reinterpret_cast<const float4*>(W)[s0 + 4];   // i0+1
        __half2 h[4];
        h[0] = __floats2half2_rn(wa.x, wa.y);
        h[1] = __floats2half2_rn(wa.z, wa.w);
        h[2] = __floats2half2_rn(wb.x, wb.y);
        h[3] = __floats2half2_rn(wb.z, wb.w);
        reinterpret_cast<float4*>(W_half)[o] = *reinterpret_cast<float4*>(h);
    }
}

__global__ __launch_bounds__(TPB, 1)
void caps_routing_reg_kernel(const float* __restrict__ inp,
                             float* __restrict__ out)
{
    __shared__ float RED[16 * 32];   // [warp][batch(2)][u(16)] s-partials
    __shared__ float WRED[32];       // per-warp S partials [2][16]
    __shared__ float VS[32];         // v[2][16]

    const int t    = threadIdx.x;
    const int lane = t & 31;
    const int warp = t >> 5;
    const int u4   = t & 3;          // u chunk this thread owns
    const int gg   = t >> 2;         // row group 0..127  (= warp*8 + g3)
    const int cc   = blockIdx.x;     // output capsule
    const int b0   = blockIdx.y << 1;

    float u0[KROWS][4], u1[KROWS][4];   // u_hat chunks (fp32), both batches
    float a0[KROWS], a1[KROWS];         // agreement logits (log2 domain)

    // ================= Phase 0: u_hat via HFMA2 (in-register F2FP dup) ======
    {
        const float4* W4 = reinterpret_cast<const float4*>(W_half);
        #pragma unroll
        for (int k = 0; k < KROWS; ++k) {
            const int n = gg + (k << 7);
            const float4* ip0 = reinterpret_cast<const float4*>(inp + ((size_t)b0       * NN + n) * DIN);
            const float4* ip1 = reinterpret_cast<const float4*>(inp + ((size_t)(b0 + 1) * NN + n) * DIN);
            float4 x0 = ip0[0], x1 = ip0[1];
            float4 y0 = ip1[0], y1 = ip1[1];
            // duplicated half2 inputs: 1 F2FP.PACK each
            __half2 da[8], db[8];
            da[0] = __floats2half2_rn(x0.x, x0.x);
            da[1] = __floats2half2_rn(x0.y, x0.y);
            da[2] = __floats2half2_rn(x0.z, x0.z);
            da[3] = __floats2half2_rn(x0.w, x0.w);
            da[4] = __floats2half2_rn(x1.x, x1.x);
            da[5] = __floats2half2_rn(x1.y, x1.y);
            da[6] = __floats2half2_rn(x1.z, x1.z);
            da[7] = __floats2half2_rn(x1.w, x1.w);
            db[0] = __floats2half2_rn(y0.x, y0.x);
            db[1] = __floats2half2_rn(y0.y, y0.y);
            db[2] = __floats2half2_rn(y0.z, y0.z);
            db[3] = __floats2half2_rn(y0.w, y0.w);
            db[4] = __floats2half2_rn(y1.x, y1.x);
            db[5] = __floats2half2_rn(y1.y, y1.y);
            db[6] = __floats2half2_rn(y1.z, y1.z);
            db[7] = __floats2half2_rn(y1.w, y1.w);

            const size_t wbase = ((((size_t)cc * 9 + k) * 16 + warp) * 4) * 32 + lane;

            // half2 accumulators: l = i 0..3 (m=0,1), h = i 4..7 (m=2,3)
            __half2 l01_0, l23_0, h01_0, h23_0;   // batch 0
            __half2 l01_1, l23_1, h01_1, h23_1;   // batch 1
            #pragma unroll
            for (int m = 0; m < 4; ++m) {
                float4 wq = W4[wbase + m * 32];   // warp-contiguous 512B
                const __half2* hh = reinterpret_cast<const __half2*>(&wq);
                const __half2 e0 = da[2 * m], e1 = da[2 * m + 1];
                const __half2 f0 = db[2 * m], f1 = db[2 * m + 1];
                if (m == 0) {
                    l01_0 = __hmul2(hh[0], e0);  l23_0 = __hmul2(hh[1], e0);
                    l01_1 = __hmul2(hh[0], f0);  l23_1 = __hmul2(hh[1], f0);
                    l01_0 = __hfma2(hh[2], e1, l01_0);  l23_0 = __hfma2(hh[3], e1, l23_0);
                    l01_1 = __hfma2(hh[2], f1, l01_1);  l23_1 = __hfma2(hh[3], f1, l23_1);
                } else if (m == 1) {
                    l01_0 = __hfma2(hh[0], e0, l01_0);  l23_0 = __hfma2(hh[1], e0, l23_0);
                    l01_1 = __hfma2(hh[0], f0, l01_1);  l23_1 = __hfma2(hh[1], f0, l23_1);
                    l01_0 = __hfma2(hh[2], e1, l01_0);  l23_0 = __hfma2(hh[3], e1, l23_0);
                    l01_1 = __hfma2(hh[2], f1, l01_1);  l23_1 = __hfma2(hh[3], f1, l23_1);
                } else if (m == 2) {
                    h01_0 = __hmul2(hh[0], e0);  h23_0 = __hmul2(hh[1], e0);
                    h01_1 = __hmul2(hh[0], f0);  h23_1 = __hmul2(hh[1], f0);
                    h01_0 = __hfma2(hh[2], e1, h01_0);  h23_0 = __hfma2(hh[3], e1, h23_0);
                    h01_1 = __hfma2(hh[2], f1, h01_1);  h23_1 = __hfma2(hh[3], f1, h23_1);
                } else {
                    h01_0 = __hfma2(hh[0], e0, h01_0);  h23_0 = __hfma2(hh[1], e0, h23_0);
                    h01_1 = __hfma2(hh[0], f0, h01_1);  h23_1 = __hfma2(hh[1], f0, h23_1);
                    h01_0 = __hfma2(hh[2], e1, h01_0);  h23_0 = __hfma2(hh[3], e1, h23_0);
                    h01_1 = __hfma2(hh[2], f1, h01_1);  h23_1 = __hfma2(hh[3], f1, h23_1);
                }
            }
            // combine the two 4-term half chains in fp32
            float2 a01l = __half22float2(l01_0), a01h = __half22float2(h01_0);
            float2 a23l = __half22float2(l23_0), a23h = __half22float2(h23_0);
            u0[k][0] = a01l.x + a01h.x;  u0[k][1] = a01l.y + a01h.y;
            u0[k][2] = a23l.x + a23h.x;  u0[k][3] = a23l.y + a23h.y;
            float2 b01l = __half22float2(l01_1), b01h = __half22float2(h01_1);
            float2 b23l = __half22float2(l23_1), b23h = __half22float2(h23_1);
            u1[k][0] = b01l.x + b01h.x;  u1[k][1] = b01l.y + b01h.y;
            u1[k][2] = b23l.x + b23h.x;  u1[k][3] = b23l.y + b23h.y;
        }
    }

    // ================= Dynamic routing (3 iterations) =================
    // Initial logits b=1 drop out of softmax. Logits in log2 units
    // (v scaled by log2e in phase C) so cw = ex2(a) is one MUFU op.
    for (int it = 0; it < 3; ++it) {
        // ---- Phase A: s[u] partials + S partial ----
        {
            float s0[4] = {0.f, 0.f, 0.f, 0.f};
            float s1[4] = {0.f, 0.f, 0.f, 0.f};
            float ls0 = 0.f, ls1 = 0.f;
            #pragma unroll
            for (int k = 0; k < KROWS; ++k) {
                const float cw0 = (it == 0) ? 1.0f : ex2f(a0[k]);
                const float cw1 = (it == 0) ? 1.0f : ex2f(a1[k]);
                ls0 += cw0;  ls1 += cw1;
                #pragma unroll
                for (int j = 0; j < 4; ++j) {
                    s0[j] += cw0 * u0[k][j];
                    s1[j] += cw1 * u1[k][j];
                }
            }
            // butterfly over the 8 gg groups within this warp (same u4)
            #pragma unroll
            for (int off = 4; off <= 16; off <<= 1) {
                #pragma unroll
                for (int j = 0; j < 4; ++j) {
                    s0[j] += __shfl_xor_sync(0xffffffffu, s0[j], off);
                    s1[j] += __shfl_xor_sync(0xffffffffu, s1[j], off);
                }
                ls0 += __shfl_xor_sync(0xffffffffu, ls0, off);
                ls1 += __shfl_xor_sync(0xffffffffu, ls1, off);
            }
            if (lane < 4) {
                *reinterpret_cast<float4*>(&RED[warp * 32 +      u4 * 4]) = make_float4(s0[0], s0[1], s0[2], s0[3]);
                *reinterpret_cast<float4*>(&RED[warp * 32 + 16 + u4 * 4]) = make_float4(s1[0], s1[1], s1[2], s1[3]);
            }
            if (lane == 0) { WRED[warp] = ls0; WRED[16 + warp] = ls1; }
        }
        __syncthreads();

        // ---- Phase B: warp 0 finalizes s, squash -> v ----
        if (warp == 0) {
            const int q = lane >> 4;     // batch within pair
            const int u = lane & 15;
            float s = 0.f;
            #pragma unroll
            for (int w = 0; w < 16; ++w) s += RED[w * 32 + lane];
            float S;
            if (it == 0) S = (float)NN;
            else {
                S = 0.f;
                #pragma unroll
                for (int w = 0; w < 16; ++w) S += WRED[q * 16 + w];
            }
            s /= S;
            float sq = s * s;
            #pragma unroll
            for (int off = 1; off <= 8; off <<= 1) sq += __shfl_xor_sync(0xffffffffu, sq, off);
            const float scale = sq / ((1.0f + sq) * sqrtf(sq + 1e-9f));
            const float v = scale * s;
            VS[lane] = v;
            if (it == 2) out[((size_t)(b0 + q) * NC + cc) * NU + u] = v;
        }
        if (it == 2) return;
        __syncthreads();

        // ---- Phase C: a[n] += log2e * (u_hat[n] . v) (quad reduction) ----
        {
            const float LOG2E = 1.4426950408889634f;
            float4 v0 = *reinterpret_cast<const float4*>(&VS[u4 * 4]);
            float4 v1 = *reinterpret_cast<const float4*>(&VS[16 + u4 * 4]);
            v0.x *= LOG2E; v0.y *= LOG2E; v0.z *= LOG2E; v0.w *= LOG2E;
            v1.x *= LOG2E; v1.y *= LOG2E; v1.z *= LOG2E; v1.w *= LOG2E;
            #pragma unroll
            for (int k = 0; k < KROWS; ++k) {
                float d0 = u0[k][0] * v0.x + u0[k][1] * v0.y + u0[k][2] * v0.z + u0[k][3] * v0.w;
                float d1 = u1[k][0] * v1.x + u1[k][1] * v1.y + u1[k][2] * v1.z + u1[k][3] * v1.w;
                d0 += __shfl_xor_sync(0xffffffffu, d0, 1);
                d0 += __shfl_xor_sync(0xffffffffu, d0, 2);
                d1 += __shfl_xor_sync(0xffffffffu, d1, 1);
                d1 += __shfl_xor_sync(0xffffffffu, d1, 2);
                a0[k] = (it == 0) ? d0 : (a0[k] + d0);
                a1[k] = (it == 0) ? d1 : (a1[k] + d1);
            }
        }
        // a[] is thread-private; VS reuse is fenced by the phase-A sync.
    }
}

extern "C" void kernel_launch(void* const* d_in, const int* in_sizes, int n_in,
                              void* d_out, int out_size)
{
    const float* inp = (const float*)d_in[0];
    const float* W   = (const float*)d_in[1];
    if (n_in >= 2 && in_sizes[0] == WTOT && in_sizes[1] == INTOT) {
        const float* tmp = inp; inp = W; W = tmp;   // defensive order swap
    }
    float* out = (float*)d_out;

    // Step 1: W fp32 -> warp-contiguous fp16 scratch (16-warp layout)
    convert_W_kernel<<<720, 512>>>(W);

    // Step 2: fused routing
    dim3 grid(NC, NB / 2);   // 10 x 128 = 1280 CTAs, one batch-pair each
    caps_routing_reg_kernel<<<grid, TPB>>>(inp, out);
}